// round 1
// baseline (speedup 1.0000x reference)
#include <cuda_runtime.h>
#include <cuda_bf16.h>
#include <cstdint>

#define NB 64
#define NM 512
#define ND 2048
#define NK 32

// ---- scratch (device globals: allocation-free) ----
__device__ __nv_bfloat16 g_xraw[(size_t)NB*NM*ND];   // bf16 copy of x (unnormalized), 128 MB
__device__ __nv_bfloat16 g_sap[NB*NM*NK];            // sa * rnorm (bf16), 2 MB
__device__ float g_S[NB*NK];                         // colsum of sa (fp32)
__device__ float g_nsq[NB*NK];                       // per-(b,k) sum of squares of vlad
__device__ float g_vlad[NB*NK*ND];                   // un-normalized vlad, 16 MB

__device__ __forceinline__ void mma_bf16(float c[4],
    unsigned a0, unsigned a1, unsigned a2, unsigned a3,
    unsigned b0, unsigned b1) {
  asm volatile(
    "mma.sync.aligned.m16n8k16.row.col.f32.bf16.bf16.f32 "
    "{%0,%1,%2,%3}, {%4,%5,%6,%7}, {%8,%9}, {%0,%1,%2,%3};\n"
    : "+f"(c[0]), "+f"(c[1]), "+f"(c[2]), "+f"(c[3])
    : "r"(a0), "r"(a1), "r"(a2), "r"(a3), "r"(b0), "r"(b1));
}

// ================= KZ: zero the accumulators =================
__global__ void kz_kernel() {
  int i = blockIdx.x * blockDim.x + threadIdx.x;
  if (i < NB * NK) { g_S[i] = 0.f; g_nsq[i] = 0.f; }
}

// ================= KA: norm + logits + softmax (one pass over x) ========
// 64 rows per block, 256 threads (8 warps). Streams x fp32 -> bf16 (smem +
// global copy), accumulates row sumsq, logits = (x@W^T)*rsqrt(sumsq) via mma,
// softmax over K=32, writes sa' = sa*rnorm bf16 and colsum(sa) fp32 atomics.
__global__ __launch_bounds__(256) void ka_kernel(const float* __restrict__ x,
                                                 const float* __restrict__ Wm) {
  const int ROWS = 64, CH = 128, LDX = CH + 8;
  __shared__ __align__(16) __nv_bfloat16 xs[ROWS][LDX];  // x chunk (bf16)
  __shared__ __align__(16) __nv_bfloat16 ws[NK][LDX];    // W chunk (bf16)
  __shared__ float slog[ROWS][NK + 4];                   // raw logits
  __shared__ float srn[ROWS];                            // 1/||x_row||
  __shared__ float scol[NK];                             // block colsum

  const int tid = threadIdx.x, lane = tid & 31, w = tid >> 5;
  const int g = lane >> 2, q = lane & 3;
  const int r0 = blockIdx.x * ROWS;  // global row in [0, B*M)

  if (tid < NK) scol[tid] = 0.f;

  float ssq[8];
#pragma unroll
  for (int j = 0; j < 8; j++) ssq[j] = 0.f;

  // warp w: m-tile (w&3) (16 rows), n-block (w>>2)*16 (two 8-col n-tiles)
  const int mt = w & 3, nb = (w >> 2) * 16;
  float c[2][4];
#pragma unroll
  for (int i = 0; i < 2; i++) { c[i][0]=c[i][1]=c[i][2]=c[i][3]=0.f; }

  for (int ch = 0; ch < ND / CH; ch++) {
    const int c0 = ch * CH;
    // load x chunk [64][128] fp32: warp w handles rows w+8j, lane covers 4 cols
#pragma unroll
    for (int j = 0; j < 8; j++) {
      int row = w + 8 * j;
      float4 v = *reinterpret_cast<const float4*>(
          x + (size_t)(r0 + row) * ND + c0 + lane * 4);
      ssq[j] += v.x*v.x + v.y*v.y + v.z*v.z + v.w*v.w;
      __nv_bfloat162 p0, p1;
      p0.x = __float2bfloat16(v.x); p0.y = __float2bfloat16(v.y);
      p1.x = __float2bfloat16(v.z); p1.y = __float2bfloat16(v.w);
      *reinterpret_cast<__nv_bfloat162*>(&xs[row][lane * 4])     = p0;
      *reinterpret_cast<__nv_bfloat162*>(&xs[row][lane * 4 + 2]) = p1;
      uint2 pk;
      pk.x = *reinterpret_cast<unsigned*>(&p0);
      pk.y = *reinterpret_cast<unsigned*>(&p1);
      *reinterpret_cast<uint2*>(
          &g_xraw[(size_t)(r0 + row) * ND + c0 + lane * 4]) = pk;
    }
    // load W chunk [32][128] fp32 -> bf16 smem
#pragma unroll
    for (int i = 0; i < 4; i++) {
      int e = tid + 256 * i;             // float4 units, 32 per row
      int rw = e >> 5, cw = (e & 31) * 4;
      float4 v = *reinterpret_cast<const float4*>(
          Wm + (size_t)rw * ND + c0 + cw);
      __nv_bfloat162 p0, p1;
      p0.x = __float2bfloat16(v.x); p0.y = __float2bfloat16(v.y);
      p1.x = __float2bfloat16(v.z); p1.y = __float2bfloat16(v.w);
      *reinterpret_cast<__nv_bfloat162*>(&ws[rw][cw])     = p0;
      *reinterpret_cast<__nv_bfloat162*>(&ws[rw][cw + 2]) = p1;
    }
    __syncthreads();
    // mma over this chunk: 8 k-steps of 16
#pragma unroll
    for (int ks = 0; ks < CH / 16; ks++) {
      int k0 = ks * 16;
      unsigned a0 = *reinterpret_cast<unsigned*>(&xs[16*mt + g    ][k0 + 2*q]);
      unsigned a1 = *reinterpret_cast<unsigned*>(&xs[16*mt + g + 8][k0 + 2*q]);
      unsigned a2 = *reinterpret_cast<unsigned*>(&xs[16*mt + g    ][k0 + 2*q + 8]);
      unsigned a3 = *reinterpret_cast<unsigned*>(&xs[16*mt + g + 8][k0 + 2*q + 8]);
#pragma unroll
      for (int nt = 0; nt < 2; nt++) {
        unsigned b0 = *reinterpret_cast<unsigned*>(&ws[nb + 8*nt + g][k0 + 2*q]);
        unsigned b1 = *reinterpret_cast<unsigned*>(&ws[nb + 8*nt + g][k0 + 2*q + 8]);
        mma_bf16(c[nt], a0, a1, a2, a3, b0, b1);
      }
    }
    __syncthreads();
  }

  // finalize row norms
#pragma unroll
  for (int j = 0; j < 8; j++) {
    float v = ssq[j];
    v += __shfl_xor_sync(0xffffffffu, v, 16);
    v += __shfl_xor_sync(0xffffffffu, v, 8);
    v += __shfl_xor_sync(0xffffffffu, v, 4);
    v += __shfl_xor_sync(0xffffffffu, v, 2);
    v += __shfl_xor_sync(0xffffffffu, v, 1);
    if (lane == 0) srn[w + 8 * j] = rsqrtf(fmaxf(v, 1e-24f));
  }
  // dump logits to smem
#pragma unroll
  for (int nt = 0; nt < 2; nt++) {
    slog[16*mt + g    ][nb + 8*nt + 2*q]     = c[nt][0];
    slog[16*mt + g    ][nb + 8*nt + 2*q + 1] = c[nt][1];
    slog[16*mt + g + 8][nb + 8*nt + 2*q]     = c[nt][2];
    slog[16*mt + g + 8][nb + 8*nt + 2*q + 1] = c[nt][3];
  }
  __syncthreads();

  // softmax: one thread per row (threads 0..63, two full warps)
  if (tid < ROWS) {
    float rn = srn[tid];
    float l[NK];
    float mx = -1e30f;
#pragma unroll
    for (int k = 0; k < NK; k++) { l[k] = slog[tid][k] * rn; mx = fmaxf(mx, l[k]); }
    float s = 0.f;
#pragma unroll
    for (int k = 0; k < NK; k++) { l[k] = expf(l[k] - mx); s += l[k]; }
    float inv = 1.f / s;
#pragma unroll
    for (int k = 0; k < NK; k += 2) {
      float s0 = l[k] * inv, s1 = l[k + 1] * inv;
      __nv_bfloat162 p;
      p.x = __float2bfloat16(s0 * rn);
      p.y = __float2bfloat16(s1 * rn);
      *reinterpret_cast<__nv_bfloat162*>(&g_sap[(size_t)(r0 + tid) * NK + k]) = p;
    }
    // colsum(sa): reduce across the 32 rows of this warp, then smem atomic
#pragma unroll
    for (int k = 0; k < NK; k++) {
      float v = l[k] * inv;
      v += __shfl_xor_sync(0xffffffffu, v, 16);
      v += __shfl_xor_sync(0xffffffffu, v, 8);
      v += __shfl_xor_sync(0xffffffffu, v, 4);
      v += __shfl_xor_sync(0xffffffffu, v, 2);
      v += __shfl_xor_sync(0xffffffffu, v, 1);
      if (lane == 0) atomicAdd(&scol[k], v);
    }
  }
  __syncthreads();
  if (tid < NK) {
    int b = r0 / NM;
    atomicAdd(&g_S[b * NK + tid], scol[tid]);
  }
}

// ================= KB: agg GEMM + centroid subtract + sumsq =============
// Block = (b, 256-wide d chunk). C[32, 256] = sa'^T[32,512] @ x_bf16[512,256].
__global__ __launch_bounds__(256) void kb_kernel(const float* __restrict__ cent) {
  const int DN = 256, MC = 64, LDB = DN + 8, LDA = MC + 8;
  __shared__ __align__(16) __nv_bfloat16 sA[NK][LDA];   // sa'^T chunk [32][64]
  __shared__ __align__(16) __nv_bfloat16 sB[MC][LDB];   // x chunk   [64][256]
  __shared__ float sS[NK];

  const int tid = threadIdx.x, lane = tid & 31, w = tid >> 5;
  const int g = lane >> 2, q = lane & 3;
  const int b  = blockIdx.x >> 3;
  const int d0 = (blockIdx.x & 7) * DN;
  if (tid < NK) sS[tid] = g_S[b * NK + tid];

  // warp w: m-tile (w&1) (16 cluster rows), 8 n-tiles covering 64 d cols
  const int mt = w & 1, nb = (w >> 1) * 64;
  float c[8][4];
#pragma unroll
  for (int i = 0; i < 8; i++) { c[i][0]=c[i][1]=c[i][2]=c[i][3]=0.f; }

  for (int mc2 = 0; mc2 < NM / MC; mc2++) {
    int m0 = mc2 * MC;
    // load sa' chunk [64][32] and transpose -> sA[32][64]
#pragma unroll
    for (int i = 0; i < 2; i++) {
      int u = tid + 256 * i;               // 0..511, 8 x uint2 per row
      int mm = u >> 3, k4 = (u & 7) * 4;
      uint2 pk = *reinterpret_cast<const uint2*>(
          &g_sap[(size_t)(b * NM + m0 + mm) * NK + k4]);
      __nv_bfloat162 p0 = *reinterpret_cast<__nv_bfloat162*>(&pk.x);
      __nv_bfloat162 p1 = *reinterpret_cast<__nv_bfloat162*>(&pk.y);
      sA[k4 + 0][mm] = p0.x; sA[k4 + 1][mm] = p0.y;
      sA[k4 + 2][mm] = p1.x; sA[k4 + 3][mm] = p1.y;
    }
    // load x chunk [64][256] bf16 (row-major, d contiguous)
#pragma unroll
    for (int i = 0; i < 8; i++) {
      int v = tid + 256 * i;               // 16B units, 32 per row
      int mm = v >> 5, ce = (v & 31) * 8;
      uint4 dd = *reinterpret_cast<const uint4*>(
          &g_xraw[(size_t)(b * NM + m0 + mm) * ND + d0 + ce]);
      *reinterpret_cast<uint2*>(&sB[mm][ce])     = make_uint2(dd.x, dd.y);
      *reinterpret_cast<uint2*>(&sB[mm][ce + 4]) = make_uint2(dd.z, dd.w);
    }
    __syncthreads();
#pragma unroll
    for (int ks = 0; ks < MC / 16; ks++) {
      int k0 = ks * 16;
      unsigned a0 = *reinterpret_cast<unsigned*>(&sA[16*mt + g    ][k0 + 2*q]);
      unsigned a1 = *reinterpret_cast<unsigned*>(&sA[16*mt + g + 8][k0 + 2*q]);
      unsigned a2 = *reinterpret_cast<unsigned*>(&sA[16*mt + g    ][k0 + 2*q + 8]);
      unsigned a3 = *reinterpret_cast<unsigned*>(&sA[16*mt + g + 8][k0 + 2*q + 8]);
#pragma unroll
      for (int nt = 0; nt < 8; nt++) {
        unsigned b0, b1;
        unsigned addr = (unsigned)__cvta_generic_to_shared(
            &sB[k0 + (lane & 15)][nb + 8 * nt]);
        asm volatile(
            "ldmatrix.sync.aligned.m8n8.x2.trans.shared.b16 {%0,%1}, [%2];\n"
            : "=r"(b0), "=r"(b1) : "r"(addr));
        mma_bf16(c[nt], a0, a1, a2, a3, b0, b1);
      }
    }
    __syncthreads();
  }

  // epilogue: vlad = C - S_k * centroid ; per-(b,k) sumsq ; store vlad
  const int rl = 16 * mt + g, rh = rl + 8;
  const float Sl = sS[rl], Sh = sS[rh];
  float sql = 0.f, sqh = 0.f;
#pragma unroll
  for (int nt = 0; nt < 8; nt++) {
    int col = d0 + nb + 8 * nt + 2 * q;
    float2 cl = *reinterpret_cast<const float2*>(cent + (size_t)rl * ND + col);
    float2 ch = *reinterpret_cast<const float2*>(cent + (size_t)rh * ND + col);
    float v0 = c[nt][0] - Sl * cl.x, v1 = c[nt][1] - Sl * cl.y;
    float v2 = c[nt][2] - Sh * ch.x, v3 = c[nt][3] - Sh * ch.y;
    sql += v0 * v0 + v1 * v1;
    sqh += v2 * v2 + v3 * v3;
    float2 o0; o0.x = v0; o0.y = v1;
    float2 o1; o1.x = v2; o1.y = v3;
    *reinterpret_cast<float2*>(&g_vlad[(size_t)(b * NK + rl) * ND + col]) = o0;
    *reinterpret_cast<float2*>(&g_vlad[(size_t)(b * NK + rh) * ND + col]) = o1;
  }
  sql += __shfl_xor_sync(0xffffffffu, sql, 1);
  sql += __shfl_xor_sync(0xffffffffu, sql, 2);
  sqh += __shfl_xor_sync(0xffffffffu, sqh, 1);
  sqh += __shfl_xor_sync(0xffffffffu, sqh, 2);
  if (q == 0) {
    atomicAdd(&g_nsq[b * NK + rl], sql);
    atomicAdd(&g_nsq[b * NK + rh], sqh);
  }
}

// ================= KC: final scaling ====================================
// intra-normalize by rsqrt(nsq); final L2 over K*D is exactly sqrt(K)
__global__ __launch_bounds__(256) void kc_kernel(float* __restrict__ out) {
  int i4 = blockIdx.x * 256 + threadIdx.x;
  int e = i4 * 4;
  int row = e >> 11;  // = b*K + k
  float ns = g_nsq[row];
  float sc = rsqrtf(fmaxf(ns, 1e-24f) * 32.0f);
  float4 v = *reinterpret_cast<float4*>(&g_vlad[e]);
  v.x *= sc; v.y *= sc; v.z *= sc; v.w *= sc;
  *reinterpret_cast<float4*>(out + e) = v;
}

extern "C" void kernel_launch(void* const* d_in, const int* in_sizes, int n_in,
                              void* d_out, int out_size) {
  const float* x    = (const float*)d_in[0];
  const float* Wm   = (const float*)d_in[1];
  const float* cent = (const float*)d_in[2];
  float* out = (float*)d_out;

  kz_kernel<<<8, 256>>>();
  ka_kernel<<<(NB * NM) / 64, 256>>>(x, Wm);
  kb_kernel<<<NB * 8, 256>>>(cent);
  kc_kernel<<<(NB * NK * ND) / (256 * 4), 256>>>(out);
}

// round 2
// speedup vs baseline: 2.2003x; 2.2003x over previous
#include <cuda_runtime.h>
#include <cuda_bf16.h>
#include <cstdint>

#define NB 64
#define NM 512
#define ND 2048
#define NK 32

// ---- scratch (device globals: allocation-free) ----
__device__ __align__(256) __nv_bfloat16 g_xraw[(size_t)NB*NM*ND];  // bf16 x copy
__device__ __align__(256) __nv_bfloat16 g_sap[NB*NM*NK];           // sa * rnorm
__device__ float g_S[NB*NK];
__device__ float g_nsq[NB*NK];
__device__ __align__(256) float g_vlad[NB*NK*ND];

__device__ __forceinline__ void mma_bf16(float c[4],
    unsigned a0, unsigned a1, unsigned a2, unsigned a3,
    unsigned b0, unsigned b1) {
  asm volatile(
    "mma.sync.aligned.m16n8k16.row.col.f32.bf16.bf16.f32 "
    "{%0,%1,%2,%3}, {%4,%5,%6,%7}, {%8,%9}, {%0,%1,%2,%3};\n"
    : "+f"(c[0]), "+f"(c[1]), "+f"(c[2]), "+f"(c[3])
    : "r"(a0), "r"(a1), "r"(a2), "r"(a3), "r"(b0), "r"(b1));
}

__device__ __forceinline__ void cp16(void* dst, const void* src) {
  unsigned d = (unsigned)__cvta_generic_to_shared(dst);
  asm volatile("cp.async.cg.shared.global [%0], [%1], 16;\n" :: "r"(d), "l"(src));
}
__device__ __forceinline__ void cp_commit() {
  asm volatile("cp.async.commit_group;\n");
}
__device__ __forceinline__ void cp_wait1() {
  asm volatile("cp.async.wait_group 1;\n");
}

// ================= KZ =================
__global__ void kz_kernel() {
  int i = blockIdx.x * blockDim.x + threadIdx.x;
  if (i < NB * NK) { g_S[i] = 0.f; g_nsq[i] = 0.f; }
}

// ================= KA: norm + logits + softmax, cp.async pipelined ========
// 64 rows/block, 256 threads. Chunk = 64 cols, 32 iters, double-buffered.
#define KA_XS 72   // fp32 smem row stride (floats): 36 mod 32 == 4 -> conflict-free frags
#define KA_WS 72   // bf16 smem row stride (halves)
#define KA_XBYTES (2*64*KA_XS*4)           // 36864
#define KA_WBYTES (2*32*KA_WS*2)           // 9216
__global__ __launch_bounds__(256) void ka_kernel(const float* __restrict__ x,
                                                 const float* __restrict__ Wm) {
  __shared__ __align__(16) char blob[KA_XBYTES + KA_WBYTES];
  float* xf = reinterpret_cast<float*>(blob);                 // [2][64][72]
  __nv_bfloat16* wb = reinterpret_cast<__nv_bfloat16*>(blob + KA_XBYTES); // [2][32][72]
  float (*slog)[36] = reinterpret_cast<float(*)[36]>(blob);   // alias (post-loop only)
  __shared__ float srn[64];

  const int tid = threadIdx.x, lane = tid & 31, w = tid >> 5;
  const int g = lane >> 2, q = lane & 3;
  const int r0 = blockIdx.x * 64;
  const int mt = w & 3, nbase = (w >> 2) * 16;

  float ssq = 0.f;
  float c[2][4];
#pragma unroll
  for (int i = 0; i < 2; i++) { c[i][0]=c[i][1]=c[i][2]=c[i][3]=0.f; }

  const int crow = tid >> 2, cseg = (tid & 3) * 16;   // convert-phase assignment
  const int wrw = tid >> 3, wcw = (tid & 7) * 8;      // W-load assignment

  // prologue: chunk 0
  {
#pragma unroll
    for (int j = 0; j < 4; j++) {
      int op = tid + 256 * j;
      int row = op >> 4, seg = op & 15;
      cp16(xf + row * KA_XS + seg * 4,
           x + (size_t)(r0 + row) * ND + seg * 4);
    }
    cp_commit();
    float4 wv0 = *reinterpret_cast<const float4*>(Wm + (size_t)wrw * ND + wcw);
    float4 wv1 = *reinterpret_cast<const float4*>(Wm + (size_t)wrw * ND + wcw + 4);
    __nv_bfloat162 h0 = __float22bfloat162_rn(make_float2(wv0.x, wv0.y));
    __nv_bfloat162 h1 = __float22bfloat162_rn(make_float2(wv0.z, wv0.w));
    __nv_bfloat162 h2 = __float22bfloat162_rn(make_float2(wv1.x, wv1.y));
    __nv_bfloat162 h3 = __float22bfloat162_rn(make_float2(wv1.z, wv1.w));
    uint4 pk;
    pk.x = *reinterpret_cast<unsigned*>(&h0); pk.y = *reinterpret_cast<unsigned*>(&h1);
    pk.z = *reinterpret_cast<unsigned*>(&h2); pk.w = *reinterpret_cast<unsigned*>(&h3);
    *reinterpret_cast<uint4*>(wb + wrw * KA_WS + wcw) = pk;
  }

  for (int it = 0; it < 32; it++) {
    const int buf = it & 1, nbuf = buf ^ 1;
    float4 wv0, wv1;
    const bool more = (it + 1 < 32);
    if (more) {
      const int c1 = (it + 1) * 64;
#pragma unroll
      for (int j = 0; j < 4; j++) {
        int op = tid + 256 * j;
        int row = op >> 4, seg = op & 15;
        cp16(xf + nbuf * (64 * KA_XS) + row * KA_XS + seg * 4,
             x + (size_t)(r0 + row) * ND + c1 + seg * 4);
      }
      wv0 = *reinterpret_cast<const float4*>(Wm + (size_t)wrw * ND + c1 + wcw);
      wv1 = *reinterpret_cast<const float4*>(Wm + (size_t)wrw * ND + c1 + wcw + 4);
    }
    cp_commit();
    cp_wait1();
    __syncthreads();

    // ---- compute on chunk it ----
    const float* xb = xf + buf * (64 * KA_XS);
    const __nv_bfloat16* wbb = wb + buf * (32 * KA_WS);

    // convert + sumsq + bf16 global store
    {
      const float* src = xb + crow * KA_XS + cseg;
      float4 v0 = *reinterpret_cast<const float4*>(src);
      float4 v1 = *reinterpret_cast<const float4*>(src + 4);
      float4 v2 = *reinterpret_cast<const float4*>(src + 8);
      float4 v3 = *reinterpret_cast<const float4*>(src + 12);
      ssq += v0.x*v0.x + v0.y*v0.y + v0.z*v0.z + v0.w*v0.w
           + v1.x*v1.x + v1.y*v1.y + v1.z*v1.z + v1.w*v1.w
           + v2.x*v2.x + v2.y*v2.y + v2.z*v2.z + v2.w*v2.w
           + v3.x*v3.x + v3.y*v3.y + v3.z*v3.z + v3.w*v3.w;
      __nv_bfloat162 p0 = __float22bfloat162_rn(make_float2(v0.x, v0.y));
      __nv_bfloat162 p1 = __float22bfloat162_rn(make_float2(v0.z, v0.w));
      __nv_bfloat162 p2 = __float22bfloat162_rn(make_float2(v1.x, v1.y));
      __nv_bfloat162 p3 = __float22bfloat162_rn(make_float2(v1.z, v1.w));
      __nv_bfloat162 p4 = __float22bfloat162_rn(make_float2(v2.x, v2.y));
      __nv_bfloat162 p5 = __float22bfloat162_rn(make_float2(v2.z, v2.w));
      __nv_bfloat162 p6 = __float22bfloat162_rn(make_float2(v3.x, v3.y));
      __nv_bfloat162 p7 = __float22bfloat162_rn(make_float2(v3.z, v3.w));
      uint4 o0, o1;
      o0.x = *reinterpret_cast<unsigned*>(&p0); o0.y = *reinterpret_cast<unsigned*>(&p1);
      o0.z = *reinterpret_cast<unsigned*>(&p2); o0.w = *reinterpret_cast<unsigned*>(&p3);
      o1.x = *reinterpret_cast<unsigned*>(&p4); o1.y = *reinterpret_cast<unsigned*>(&p5);
      o1.z = *reinterpret_cast<unsigned*>(&p6); o1.w = *reinterpret_cast<unsigned*>(&p7);
      __nv_bfloat16* dst = g_xraw + (size_t)(r0 + crow) * ND + it * 64 + cseg;
      *reinterpret_cast<uint4*>(dst)     = o0;
      *reinterpret_cast<uint4*>(dst + 8) = o1;
    }

    // mma over this chunk: 4 k-steps of 16
#pragma unroll
    for (int ks = 0; ks < 4; ks++) {
      const int k0 = ks * 16;
      const int rl = 16 * mt + g;
      float2 pa = *reinterpret_cast<const float2*>(xb + rl * KA_XS + k0 + 2*q);
      float2 pb = *reinterpret_cast<const float2*>(xb + (rl+8) * KA_XS + k0 + 2*q);
      float2 pc = *reinterpret_cast<const float2*>(xb + rl * KA_XS + k0 + 2*q + 8);
      float2 pd = *reinterpret_cast<const float2*>(xb + (rl+8) * KA_XS + k0 + 2*q + 8);
      __nv_bfloat162 ha = __float22bfloat162_rn(pa);
      __nv_bfloat162 hb = __float22bfloat162_rn(pb);
      __nv_bfloat162 hc = __float22bfloat162_rn(pc);
      __nv_bfloat162 hd = __float22bfloat162_rn(pd);
      unsigned a0 = *reinterpret_cast<unsigned*>(&ha);
      unsigned a1 = *reinterpret_cast<unsigned*>(&hb);
      unsigned a2 = *reinterpret_cast<unsigned*>(&hc);
      unsigned a3 = *reinterpret_cast<unsigned*>(&hd);
#pragma unroll
      for (int nt = 0; nt < 2; nt++) {
        unsigned b0 = *reinterpret_cast<const unsigned*>(
            wbb + (nbase + 8*nt + g) * KA_WS + k0 + 2*q);
        unsigned b1 = *reinterpret_cast<const unsigned*>(
            wbb + (nbase + 8*nt + g) * KA_WS + k0 + 2*q + 8);
        mma_bf16(c[nt], a0, a1, a2, a3, b0, b1);
      }
    }

    // stage W(it+1) into the other buffer
    if (more) {
      __nv_bfloat162 h0 = __float22bfloat162_rn(make_float2(wv0.x, wv0.y));
      __nv_bfloat162 h1 = __float22bfloat162_rn(make_float2(wv0.z, wv0.w));
      __nv_bfloat162 h2 = __float22bfloat162_rn(make_float2(wv1.x, wv1.y));
      __nv_bfloat162 h3 = __float22bfloat162_rn(make_float2(wv1.z, wv1.w));
      uint4 pk;
      pk.x = *reinterpret_cast<unsigned*>(&h0); pk.y = *reinterpret_cast<unsigned*>(&h1);
      pk.z = *reinterpret_cast<unsigned*>(&h2); pk.w = *reinterpret_cast<unsigned*>(&h3);
      *reinterpret_cast<uint4*>(wb + nbuf * (32 * KA_WS) + wrw * KA_WS + wcw) = pk;
    }
    __syncthreads();
  }

  // row norms: reduce across the 4 threads owning each row
  ssq += __shfl_xor_sync(0xffffffffu, ssq, 1);
  ssq += __shfl_xor_sync(0xffffffffu, ssq, 2);
  if ((tid & 3) == 0) srn[crow] = rsqrtf(fmaxf(ssq, 1e-24f));

  // dump logits into slog (aliases xf; main loop is done)
#pragma unroll
  for (int nt = 0; nt < 2; nt++) {
    slog[16*mt + g    ][nbase + 8*nt + 2*q]     = c[nt][0];
    slog[16*mt + g    ][nbase + 8*nt + 2*q + 1] = c[nt][1];
    slog[16*mt + g + 8][nbase + 8*nt + 2*q]     = c[nt][2];
    slog[16*mt + g + 8][nbase + 8*nt + 2*q + 1] = c[nt][3];
  }
  __syncthreads();

  // softmax: one thread per row; write sa' bf16; leave sa (fp32) in slog
  if (tid < 64) {
    float rn = srn[tid];
    float l[NK];
    float mx = -1e30f;
#pragma unroll
    for (int k = 0; k < NK; k++) { l[k] = slog[tid][k] * rn; mx = fmaxf(mx, l[k]); }
    float s = 0.f;
#pragma unroll
    for (int k = 0; k < NK; k++) { l[k] = expf(l[k] - mx); s += l[k]; }
    float inv = 1.f / s;
#pragma unroll
    for (int k = 0; k < NK; k++) l[k] *= inv;
#pragma unroll
    for (int k = 0; k < NK; k += 8) {
      __nv_bfloat162 q0 = __float22bfloat162_rn(make_float2(l[k]*rn,   l[k+1]*rn));
      __nv_bfloat162 q1 = __float22bfloat162_rn(make_float2(l[k+2]*rn, l[k+3]*rn));
      __nv_bfloat162 q2 = __float22bfloat162_rn(make_float2(l[k+4]*rn, l[k+5]*rn));
      __nv_bfloat162 q3 = __float22bfloat162_rn(make_float2(l[k+6]*rn, l[k+7]*rn));
      uint4 pk;
      pk.x = *reinterpret_cast<unsigned*>(&q0); pk.y = *reinterpret_cast<unsigned*>(&q1);
      pk.z = *reinterpret_cast<unsigned*>(&q2); pk.w = *reinterpret_cast<unsigned*>(&q3);
      *reinterpret_cast<uint4*>(&g_sap[(size_t)(r0 + tid) * NK + k]) = pk;
    }
#pragma unroll
    for (int k = 0; k < NK; k++) slog[tid][k] = l[k];
  }
  __syncthreads();

  // colsum: thread k sums 64 rows, one atomic per (b,k)
  if (tid < NK) {
    float s = 0.f;
#pragma unroll
    for (int r = 0; r < 64; r++) s += slog[r][tid];
    atomicAdd(&g_S[(r0 / NM) * NK + tid], s);
  }
}

// ================= KB: agg GEMM, cp.async pipelined ======================
// Block = (b, 256-wide d chunk). MC=32 m rows per stage, 16 stages, 2 bufs.
#define KB_SBS 264   // x tile stride (halves)
#define KB_SAS 40    // sa'^T tile stride (halves)
__global__ __launch_bounds__(256) void kb_kernel(const float* __restrict__ cent) {
  __shared__ __align__(16) __nv_bfloat16 sB[2][32][KB_SBS];
  __shared__ __align__(16) __nv_bfloat16 sA[2][NK][KB_SAS];
  __shared__ float sS[NK];

  const int tid = threadIdx.x, lane = tid & 31, w = tid >> 5;
  const int g = lane >> 2, q = lane & 3;
  const int b  = blockIdx.x >> 3;
  const int d0 = (blockIdx.x & 7) * 256;
  if (tid < NK) sS[tid] = g_S[b * NK + tid];

  const int mt = w & 1, nbase = (w >> 1) * 64;
  const int arow = tid >> 2, aseg = tid & 3;   // sa' load assignment (tid<128)
  float c[8][4];
#pragma unroll
  for (int i = 0; i < 8; i++) { c[i][0]=c[i][1]=c[i][2]=c[i][3]=0.f; }

  // prologue: stage 0
  {
#pragma unroll
    for (int j = 0; j < 4; j++) {
      int op = tid + 256 * j;
      int row = op >> 5, seg = op & 31;
      cp16(&sB[0][row][seg * 8],
           g_xraw + (size_t)(b * NM + row) * ND + d0 + seg * 8);
    }
    cp_commit();
    if (tid < 128) {
      uint4 pk = *reinterpret_cast<const uint4*>(
          &g_sap[(size_t)(b * NM + arow) * NK + aseg * 8]);
      const __nv_bfloat16* hp = reinterpret_cast<const __nv_bfloat16*>(&pk);
#pragma unroll
      for (int jj = 0; jj < 8; jj++) sA[0][aseg * 8 + jj][arow] = hp[jj];
    }
  }

  for (int it = 0; it < 16; it++) {
    const int buf = it & 1, nbuf = buf ^ 1;
    const bool more = (it + 1 < 16);
    uint4 pk;
    if (more) {
      const int m0 = (it + 1) * 32;
#pragma unroll
      for (int j = 0; j < 4; j++) {
        int op = tid + 256 * j;
        int row = op >> 5, seg = op & 31;
        cp16(&sB[nbuf][row][seg * 8],
             g_xraw + (size_t)(b * NM + m0 + row) * ND + d0 + seg * 8);
      }
      if (tid < 128)
        pk = *reinterpret_cast<const uint4*>(
            &g_sap[(size_t)(b * NM + m0 + arow) * NK + aseg * 8]);
    }
    cp_commit();
    cp_wait1();
    __syncthreads();

    // ---- mma on stage it ----
#pragma unroll
    for (int ks = 0; ks < 2; ks++) {
      const int k0 = ks * 16;
      unsigned a0 = *reinterpret_cast<const unsigned*>(&sA[buf][16*mt + g    ][k0 + 2*q]);
      unsigned a1 = *reinterpret_cast<const unsigned*>(&sA[buf][16*mt + g + 8][k0 + 2*q]);
      unsigned a2 = *reinterpret_cast<const unsigned*>(&sA[buf][16*mt + g    ][k0 + 2*q + 8]);
      unsigned a3 = *reinterpret_cast<const unsigned*>(&sA[buf][16*mt + g + 8][k0 + 2*q + 8]);
#pragma unroll
      for (int nt = 0; nt < 8; nt++) {
        unsigned b0, b1;
        unsigned addr = (unsigned)__cvta_generic_to_shared(
            &sB[buf][k0 + (lane & 15)][nbase + 8 * nt]);
        asm volatile(
            "ldmatrix.sync.aligned.m8n8.x2.trans.shared.b16 {%0,%1}, [%2];\n"
            : "=r"(b0), "=r"(b1) : "r"(addr));
        mma_bf16(c[nt], a0, a1, a2, a3, b0, b1);
      }
    }

    if (more && tid < 128) {
      const __nv_bfloat16* hp = reinterpret_cast<const __nv_bfloat16*>(&pk);
#pragma unroll
      for (int jj = 0; jj < 8; jj++) sA[nbuf][aseg * 8 + jj][arow] = hp[jj];
    }
    __syncthreads();
  }

  // epilogue: vlad = C - S_k * centroid ; per-(b,k) sumsq ; store vlad
  const int rl = 16 * mt + g, rh = rl + 8;
  const float Sl = sS[rl], Sh = sS[rh];
  float sql = 0.f, sqh = 0.f;
#pragma unroll
  for (int nt = 0; nt < 8; nt++) {
    int col = d0 + nbase + 8 * nt + 2 * q;
    float2 cl = *reinterpret_cast<const float2*>(cent + (size_t)rl * ND + col);
    float2 ch = *reinterpret_cast<const float2*>(cent + (size_t)rh * ND + col);
    float v0 = c[nt][0] - Sl * cl.x, v1 = c[nt][1] - Sl * cl.y;
    float v2 = c[nt][2] - Sh * ch.x, v3 = c[nt][3] - Sh * ch.y;
    sql += v0 * v0 + v1 * v1;
    sqh += v2 * v2 + v3 * v3;
    float2 o0; o0.x = v0; o0.y = v1;
    float2 o1; o1.x = v2; o1.y = v3;
    *reinterpret_cast<float2*>(&g_vlad[(size_t)(b * NK + rl) * ND + col]) = o0;
    *reinterpret_cast<float2*>(&g_vlad[(size_t)(b * NK + rh) * ND + col]) = o1;
  }
  sql += __shfl_xor_sync(0xffffffffu, sql, 1);
  sql += __shfl_xor_sync(0xffffffffu, sql, 2);
  sqh += __shfl_xor_sync(0xffffffffu, sqh, 1);
  sqh += __shfl_xor_sync(0xffffffffu, sqh, 2);
  if (q == 0) {
    atomicAdd(&g_nsq[b * NK + rl], sql);
    atomicAdd(&g_nsq[b * NK + rh], sqh);
  }
}

// ================= KC: final scaling ====================================
__global__ __launch_bounds__(256) void kc_kernel(float* __restrict__ out) {
  int i4 = blockIdx.x * 256 + threadIdx.x;
  int e = i4 * 4;
  int row = e >> 11;  // = b*K + k
  float ns = g_nsq[row];
  float4 v = *reinterpret_cast<float4*>(&g_vlad[e]);
  float sc = rsqrtf(fmaxf(ns, 1e-24f) * 32.0f);
  v.x *= sc; v.y *= sc; v.z *= sc; v.w *= sc;
  *reinterpret_cast<float4*>(out + e) = v;
}

extern "C" void kernel_launch(void* const* d_in, const int* in_sizes, int n_in,
                              void* d_out, int out_size) {
  const float* x    = (const float*)d_in[0];
  const float* Wm   = (const float*)d_in[1];
  const float* cent = (const float*)d_in[2];
  float* out = (float*)d_out;

  kz_kernel<<<8, 256>>>();
  ka_kernel<<<(NB * NM) / 64, 256>>>(x, Wm);
  kb_kernel<<<NB * 8, 256>>>(cent);
  kc_kernel<<<(NB * NK * ND) / (256 * 4), 256>>>(out);
}